// round 6
// baseline (speedup 1.0000x reference)
#include <cuda_runtime.h>
#include <cuda_bf16.h>
#include <cstdint>

#define N_TOKENS  131072
#define CODE_DIM  64
#define NUM_CODES 1024

// ---------------- device scratch (no allocations allowed) ----------------
__device__ float g_counts[NUM_CODES];
__device__ float g_dw[NUM_CODES * CODE_DIM];
__device__ float g_loss;
__device__ float g_ncs[NUM_CODES];
__device__ float g_n;
__device__ __align__(16) __nv_bfloat16 g_cb_hi[NUM_CODES * CODE_DIM];
__device__ __align__(16) __nv_bfloat16 g_cb_lo[NUM_CODES * CODE_DIM];
__device__ float g_cc[NUM_CODES];   // holds ||c||^2 + 256  (screen bias pre-folded)

// ---------------- prep: zero scratch + split codebook to bf16 hi/lo + cc ----------------
__global__ void vq_prep(const float* __restrict__ codebook) {
    int i = blockIdx.x * blockDim.x + threadIdx.x;   // 65536 threads
    g_dw[i] = 0.0f;
    if (i == 0) g_loss = 0.0f;
    if (i < NUM_CODES) {
        g_counts[i] = 0.0f;
        const float* c = codebook + (size_t)i * CODE_DIM;
        float s0 = 0.0f, s1 = 0.0f;
        #pragma unroll
        for (int k = 0; k < 32; k++) {
            float v = c[k];
            s0 += v * v;
            __nv_bfloat16 h = __float2bfloat16(v);
            g_cb_hi[i * CODE_DIM + k] = h;
            g_cb_lo[i * CODE_DIM + k] = __float2bfloat16(v - __bfloat162float(h));
        }
        #pragma unroll
        for (int k = 32; k < 64; k++) {
            float v = c[k];
            s1 += v * v;
            __nv_bfloat16 h = __float2bfloat16(v);
            g_cb_hi[i * CODE_DIM + k] = h;
            g_cb_lo[i * CODE_DIM + k] = __float2bfloat16(v - __bfloat162float(h));
        }
        g_cc[i] = (s0 + s1) + 256.0f;   // bias folded for packed-key screen
    }
}

// ---------------- asm helpers ----------------
__device__ __forceinline__ void ldsm4(uint32_t (&r)[4], uint32_t addr) {
    asm volatile("ldmatrix.sync.aligned.m8n8.x4.shared.b16 {%0,%1,%2,%3}, [%4];"
                 : "=r"(r[0]), "=r"(r[1]), "=r"(r[2]), "=r"(r[3]) : "r"(addr));
}
__device__ __forceinline__ void mma16816(float (&d)[4], const uint32_t (&a)[4],
                                         const uint32_t* b) {
    asm volatile("mma.sync.aligned.m16n8k16.row.col.f32.bf16.bf16.f32 "
                 "{%0,%1,%2,%3}, {%4,%5,%6,%7}, {%8,%9}, {%0,%1,%2,%3};"
                 : "+f"(d[0]), "+f"(d[1]), "+f"(d[2]), "+f"(d[3])
                 : "r"(a[0]), "r"(a[1]), "r"(a[2]), "r"(a[3]),
                   "r"(b[0]), "r"(b[1]));
}
__device__ __forceinline__ void cp_async16(uint32_t dst, const void* src) {
    asm volatile("cp.async.cg.shared.global [%0], [%1], 16;" :: "r"(dst), "l"(src));
}
#define CP_COMMIT() asm volatile("cp.async.commit_group;")
#define CP_WAIT1()  asm volatile("cp.async.wait_group 1;" ::: "memory")
#define CP_WAIT0()  asm volatile("cp.async.wait_group 0;" ::: "memory")

// exact round-2-style d2 (sequential-FMA dot, half-split sumsq, (zz-2a)+cc)
__device__ __forceinline__ float exact_d2_g(const float* __restrict__ zrow,
                                            const float* __restrict__ c, float zz) {
    float a = 0.0f;
    for (int k = 0; k < CODE_DIM; k++) a = fmaf(zrow[k], c[k], a);
    float c0 = 0.0f, c1 = 0.0f;
    for (int k = 0; k < 32; k++)  { float v = c[k]; c0 += v * v; }
    for (int k = 32; k < 64; k++) { float v = c[k]; c1 += v * v; }
    return (zz - 2.0f * a) + (c0 + c1);
}

__device__ __forceinline__ void merge2(unsigned long long& m1, unsigned long long& m2,
                                       unsigned long long M1, unsigned long long M2) {
    unsigned long long hi = m1 > M1 ? m1 : M1;
    m1 = m1 < M1 ? m1 : M1;
    unsigned long long l2 = m2 < M2 ? m2 : M2;
    m2 = hi < l2 ? hi : l2;
}

// smem byte offsets (dynamic smem, total 119808)
#define SZ_ZT   18432            // 128 rows x 72 elems x 2B
#define OFF_ZHI 0
#define OFF_ZLO 18432
#define OFF_CHI 36864            // [2 bufs] stride SZ_ZT
#define OFF_CLO 73728            // [2 bufs] stride SZ_ZT
#define OFF_CCS 110592           // [2 bufs] stride 512
#define OFF_RED 111616           // 128 tokens x 4 wn x 16B = 8192
#define SMEM_TOTAL 119808

// ---------------- main: 3-pass bf16 mma screen + packed-key argmin + stats ----------------
// 512 threads, 16 warps as 4(M) x 4(N); block = 128 tokens x 1024 codes (8 tiles of 128).
__global__ __launch_bounds__(512, 1)
void vq_main(const float* __restrict__ z, const float* __restrict__ codebook,
             float* __restrict__ out_q, float* __restrict__ out_idx)
{
    extern __shared__ char smem_raw[];
    const uint32_t sbase = (uint32_t)__cvta_generic_to_shared(smem_raw);

    const int tid = threadIdx.x;
    const int token0 = blockIdx.x * 128;
    const int lane = tid & 31, wid = tid >> 5;
    const int wm = wid >> 2, wn = wid & 3;
    const int lrow = lane & 7, lmat = lane >> 3;
    const int g = lane >> 2, q4 = lane & 3;

    // ---- prefetch codebook tile 0 (cp.async, buf 0) ----
    {
        #pragma unroll
        for (int j = 0; j < 4; j++) {
            int c = tid + j * 512;               // 0..2047
            int arr = c >> 10;                   // 0: hi, 1: lo
            int r = (c >> 3) & 127, k16 = c & 7;
            const __nv_bfloat16* src = (arr ? g_cb_lo : g_cb_hi) + (size_t)r * 64 + k16 * 8;
            uint32_t dst = sbase + (arr ? OFF_CLO : OFF_CHI) + r * 144 + k16 * 16;
            cp_async16(dst, src);
        }
        if (tid < 32) cp_async16(sbase + OFF_CCS + tid * 16, g_cc + tid * 4);
        CP_COMMIT();
    }

    // ---- z tile: bf16 hi/lo split into smem ----
    {
        int r = tid >> 2, h = tid & 3;           // 4 threads per token row
        const float4* zp = (const float4*)(z + (size_t)(token0 + r) * CODE_DIM) + h * 4;
        __nv_bfloat16* zhi = (__nv_bfloat16*)(smem_raw + OFF_ZHI) + r * 72 + h * 16;
        __nv_bfloat16* zlo = (__nv_bfloat16*)(smem_raw + OFF_ZLO) + r * 72 + h * 16;
        #pragma unroll
        for (int v = 0; v < 4; v++) {
            float4 t4 = zp[v];
            float vals[4] = {t4.x, t4.y, t4.z, t4.w};
            #pragma unroll
            for (int e = 0; e < 4; e++) {
                float x = vals[e];
                __nv_bfloat16 hh = __float2bfloat16(x);
                zhi[v * 4 + e] = hh;
                zlo[v * 4 + e] = __float2bfloat16(x - __bfloat162float(hh));
            }
        }
    }

    // ldmatrix addressing (same proven mapping as R4)
    const int a_row = wm * 32 + (lmat & 1) * 8 + lrow;
    const int a_kof = (lmat >> 1) * 8;
    const int b_row = wn * 32 + (lmat >> 1) * 8 + lrow;
    const int b_kof = (lmat & 1) * 8;

    // packed-key top-2 trackers: [4 rows][2 c], int32 keys (bits(s+256)&~31 | id5)
    int k1[4][2], k2[4][2];
    #pragma unroll
    for (int r = 0; r < 4; r++)
        #pragma unroll
        for (int c = 0; c < 2; c++) { k1[r][c] = 0x7FFFFFFF; k2[r][c] = 0x7FFFFFFF; }

    for (int ct = 0; ct < 8; ct++) {
        const int b = ct & 1;
        if (ct < 7) {
            const int nb = b ^ 1;
            #pragma unroll
            for (int j = 0; j < 4; j++) {
                int c = tid + j * 512;
                int arr = c >> 10;
                int r = (c >> 3) & 127, k16 = c & 7;
                const __nv_bfloat16* src = (arr ? g_cb_lo : g_cb_hi)
                                           + (size_t)((ct + 1) * 128 + r) * 64 + k16 * 8;
                uint32_t dst = sbase + (arr ? OFF_CLO : OFF_CHI) + nb * SZ_ZT + r * 144 + k16 * 16;
                cp_async16(dst, src);
            }
            if (tid < 32) cp_async16(sbase + OFF_CCS + nb * 512 + tid * 16,
                                     g_cc + (ct + 1) * 128 + tid * 4);
            CP_COMMIT();
            CP_WAIT1();
        } else {
            CP_WAIT0();
        }
        __syncthreads();

        // per-thread cc (+256 already folded)
        const float* ccs = (const float*)(smem_raw + OFF_CCS + b * 512);
        float ccr[8];
        #pragma unroll
        for (int nf = 0; nf < 4; nf++)
            #pragma unroll
            for (int c = 0; c < 2; c++)
                ccr[nf * 2 + c] = ccs[wn * 32 + nf * 8 + q4 * 2 + c];

        float acc[2][4][4];
        #pragma unroll
        for (int mf = 0; mf < 2; mf++)
            #pragma unroll
            for (int nf = 0; nf < 4; nf++)
                #pragma unroll
                for (int e = 0; e < 4; e++) acc[mf][nf][e] = 0.0f;

        const uint32_t s_chi = sbase + OFF_CHI + b * SZ_ZT;
        const uint32_t s_clo = sbase + OFF_CLO + b * SZ_ZT;

        #pragma unroll
        for (int kc = 0; kc < 4; kc++) {
            uint32_t ahi[2][4], alo[2][4], bhi[2][4], blo[2][4];
            #pragma unroll
            for (int mf = 0; mf < 2; mf++) {
                uint32_t off = (uint32_t)(((a_row + mf * 16) * 72 + kc * 16 + a_kof) * 2);
                ldsm4(ahi[mf], sbase + OFF_ZHI + off);
                ldsm4(alo[mf], sbase + OFF_ZLO + off);
            }
            #pragma unroll
            for (int np = 0; np < 2; np++) {
                uint32_t off = (uint32_t)(((b_row + np * 16) * 72 + kc * 16 + b_kof) * 2);
                ldsm4(bhi[np], s_chi + off);
                ldsm4(blo[np], s_clo + off);
            }
            #pragma unroll
            for (int mf = 0; mf < 2; mf++)
                #pragma unroll
                for (int nf = 0; nf < 4; nf++) {
                    const uint32_t* bh = &bhi[nf >> 1][(nf & 1) * 2];
                    const uint32_t* bl = &blo[nf >> 1][(nf & 1) * 2];
                    mma16816(acc[mf][nf], ahi[mf], bh);   // hi*hi
                    mma16816(acc[mf][nf], ahi[mf], bl);   // hi*lo
                    mma16816(acc[mf][nf], alo[mf], bh);   // lo*hi
                }
        }

        // epilogue: key = bits(cc+256 - 2*dot) masked | id5, branch-free top-2
        const int idb = ct * 4;
        #pragma unroll
        for (int mf = 0; mf < 2; mf++)
            #pragma unroll
            for (int rr = 0; rr < 2; rr++) {
                const int row = mf * 2 + rr;
                #pragma unroll
                for (int nf = 0; nf < 4; nf++)
                    #pragma unroll
                    for (int c = 0; c < 2; c++) {
                        float s = fmaf(acc[mf][nf][rr * 2 + c], -2.0f, ccr[nf * 2 + c]);
                        int key = (__float_as_int(s) & 0xFFFFFFE0) | (idb + nf);
                        int t_ = max(k1[row][c], key);
                        k1[row][c] = min(k1[row][c], key);
                        k2[row][c] = min(k2[row][c], t_);
                    }
            }
        __syncthreads();
    }

    // ---- per-row: build 64-bit keys (quantized value | code), merge across threads ----
    ulonglong2* red = (ulonglong2*)(smem_raw + OFF_RED);
    const int base_nc = wn * 32 + q4 * 2;
    #pragma unroll
    for (int row = 0; row < 4; row++) {
        unsigned long long kk[4];
        #pragma unroll
        for (int c = 0; c < 2; c++) {
            int ka = k1[row][c], kb = k2[row][c];
            int ida = ka & 31, idb2 = kb & 31;
            unsigned long long ca = (unsigned)((ida >> 2) * 128 + (ida & 3) * 8 + base_nc + c);
            unsigned long long cb = (unsigned)((idb2 >> 2) * 128 + (idb2 & 3) * 8 + base_nc + c);
            kk[c * 2 + 0] = ((unsigned long long)(unsigned)(ka & 0xFFFFFFE0) << 10) | ca;
            kk[c * 2 + 1] = ((unsigned long long)(unsigned)(kb & 0xFFFFFFE0) << 10) | cb;
        }
        unsigned long long m1 = min(kk[0], kk[2]);
        unsigned long long m2 = min(max(kk[0], kk[2]), min(kk[1], kk[3]));
        #pragma unroll
        for (int m = 1; m <= 2; m <<= 1) {
            unsigned long long M1 = __shfl_xor_sync(0xffffffffu, m1, m);
            unsigned long long M2 = __shfl_xor_sync(0xffffffffu, m2, m);
            merge2(m1, m2, M1, M2);
        }
        if (q4 == 0) {
            int tok = wm * 32 + (row >> 1) * 16 + (row & 1) * 8 + g;
            red[tok * 4 + wn] = make_ulonglong2(m1, m2);
        }
    }
    __syncthreads();

    // ---- writer: final merge, rescore near-ties, outputs + scatter stats ----
    float lsum = 0.0f;
    if (tid < 128) {
        const int t = tid;
        ulonglong2 p = red[t * 4];
        unsigned long long f1 = p.x, f2 = p.y;
        #pragma unroll
        for (int w = 1; w < 4; w++) {
            ulonglong2 q = red[t * 4 + w];
            merge2(f1, f2, q.x, q.y);
        }
        int bi = (int)(f1 & 1023);
        const int token = token0 + t;
        const float* zrow = z + (size_t)token * CODE_DIM;

        float s1 = __int_as_float((int)(f1 >> 10));
        float s2 = __int_as_float((int)(f2 >> 10));
        if (s2 - s1 < 0.02f) {
            int bj = (int)(f2 & 1023);
            float c0 = 0.0f, c1 = 0.0f;
            for (int k = 0; k < 32; k++)  { float v = zrow[k]; c0 += v * v; }
            for (int k = 32; k < 64; k++) { float v = zrow[k]; c1 += v * v; }
            float zz = c0 + c1;
            float da = exact_d2_g(zrow, codebook + (size_t)bi * CODE_DIM, zz);
            float db = exact_d2_g(zrow, codebook + (size_t)bj * CODE_DIM, zz);
            if (db < da || (db == da && bj < bi)) bi = bj;
        }

        out_idx[token] = (float)bi;
        atomicAdd(&g_counts[bi], 1.0f);

        const float4* cb = (const float4*)(codebook + (size_t)bi * CODE_DIM);
        const float4* zp = (const float4*)zrow;
        float4* qo = (float4*)(out_q + (size_t)token * CODE_DIM);
        #pragma unroll
        for (int v = 0; v < 16; v++) {
            float4 q = cb[v];
            float4 zv = zp[v];
            int k = v * 4;
            float d0 = zv.x - q.x, d1 = zv.y - q.y, d2 = zv.z - q.z, d3 = zv.w - q.w;
            lsum += d0 * d0; lsum += d1 * d1; lsum += d2 * d2; lsum += d3 * d3;
            qo[v] = q;
            atomicAdd(&g_dw[bi * CODE_DIM + k + 0], zv.x);
            atomicAdd(&g_dw[bi * CODE_DIM + k + 1], zv.y);
            atomicAdd(&g_dw[bi * CODE_DIM + k + 2], zv.z);
            atomicAdd(&g_dw[bi * CODE_DIM + k + 3], zv.w);
        }
    }

    // ---- block reduction of commitment-loss partial ----
    #pragma unroll
    for (int o = 16; o > 0; o >>= 1) lsum += __shfl_down_sync(0xffffffffu, lsum, o);
    __shared__ float lpart[16];
    if ((tid & 31) == 0) lpart[tid >> 5] = lsum;
    __syncthreads();
    if (tid == 0) {
        float s = 0.0f;
        #pragma unroll
        for (int w = 0; w < 16; w++) s += lpart[w];
        atomicAdd(&g_loss, s);
    }
}

// ---------------- finalize 1: new_cluster_size + its sum ----------------
__global__ void vq_final_cs(const float* __restrict__ cluster_size,
                            float* __restrict__ out_cs)
{
    int t = threadIdx.x;  // 1024 threads, 1 block
    float ncs = 0.99f * cluster_size[t] + 0.01f * g_counts[t];
    out_cs[t] = ncs;
    g_ncs[t] = ncs;

    float s = ncs;
    #pragma unroll
    for (int o = 16; o > 0; o >>= 1) s += __shfl_down_sync(0xffffffffu, s, o);
    __shared__ float p[32];
    if ((t & 31) == 0) p[t >> 5] = s;
    __syncthreads();
    if (t < 32) {
        float v = p[t];
        #pragma unroll
        for (int o = 16; o > 0; o >>= 1) v += __shfl_down_sync(0xffffffffu, v, o);
        if (t == 0) g_n = v;
    }
}

// ---------------- finalize 2: new_ema_w, new_codebook, loss ----------------
__global__ void vq_final_cb(const float* __restrict__ ema_w,
                            float* __restrict__ out_ew,
                            float* __restrict__ out_cb,
                            float* __restrict__ out_loss)
{
    int i = blockIdx.x * blockDim.x + threadIdx.x;  // 65536
    float e = 0.99f * ema_w[i] + 0.01f * g_dw[i];
    out_ew[i] = e;
    int k = i >> 6;
    float n = g_n;
    float cs = (g_ncs[k] + 1e-5f) / (n + 1024.0f * 1e-5f) * n;
    out_cb[i] = e / cs;
    if (i == 0) out_loss[0] = g_loss * (1.0f / 8388608.0f);  // 2^-23 == 1/(N*D)
}

// ---------------- launch ----------------
extern "C" void kernel_launch(void* const* d_in, const int* in_sizes, int n_in,
                              void* d_out, int out_size)
{
    const float* z            = (const float*)d_in[0];
    const float* codebook     = (const float*)d_in[1];
    const float* cluster_size = (const float*)d_in[2];
    const float* ema_w        = (const float*)d_in[3];
    float* out = (float*)d_out;

    // output packing: quantized_st | indices | loss | new_codebook | new_cluster_size | new_ema_w
    const size_t OFF_Q    = 0;
    const size_t OFF_IDX  = (size_t)N_TOKENS * CODE_DIM;          // 8388608
    const size_t OFF_LOSS = OFF_IDX + N_TOKENS;                   // 8519680
    const size_t OFF_CB   = OFF_LOSS + 1;                         // 8519681
    const size_t OFF_CS   = OFF_CB + NUM_CODES * CODE_DIM;        // 8585217
    const size_t OFF_EW   = OFF_CS + NUM_CODES;                   // 8586241

    cudaFuncSetAttribute(vq_main, cudaFuncAttributeMaxDynamicSharedMemorySize, SMEM_TOTAL);

    vq_prep<<<256, 256>>>(codebook);
    vq_main<<<N_TOKENS / 128, 512, SMEM_TOTAL>>>(z, codebook, out + OFF_Q, out + OFF_IDX);
    vq_final_cs<<<1, NUM_CODES>>>(cluster_size, out + OFF_CS);
    vq_final_cb<<<(NUM_CODES * CODE_DIM) / 256, 256>>>(ema_w, out + OFF_EW,
                                                       out + OFF_CB, out + OFF_LOSS);
}

// round 9
// speedup vs baseline: 1.8022x; 1.8022x over previous
#include <cuda_runtime.h>
#include <cuda_fp16.h>
#include <cstdint>

#define N_TOKENS  131072
#define CODE_DIM  64
#define NUM_CODES 1024

// ---------------- device scratch (no allocations allowed) ----------------
__device__ float g_counts[NUM_CODES];
__device__ float g_dw[NUM_CODES * CODE_DIM];
__device__ float g_loss;
__device__ float g_ncs[NUM_CODES];
__device__ float g_n;
__device__ __align__(16) __half g_cb_h[NUM_CODES * CODE_DIM];
__device__ __align__(16) float g_cc[NUM_CODES];   // ||c||^2 + 256 (screen bias folded)

// ---------------- prep: zero scratch + fp16 codebook + cc ----------------
__global__ void vq_prep(const float* __restrict__ codebook) {
    int i = blockIdx.x * blockDim.x + threadIdx.x;   // 65536 threads
    g_dw[i] = 0.0f;
    if (i == 0) g_loss = 0.0f;
    if (i < NUM_CODES) {
        g_counts[i] = 0.0f;
        const float* c = codebook + (size_t)i * CODE_DIM;
        float s0 = 0.0f, s1 = 0.0f;
        #pragma unroll
        for (int k = 0; k < 32; k++) {
            float v = c[k];
            s0 += v * v;
            g_cb_h[i * CODE_DIM + k] = __float2half(v);
        }
        #pragma unroll
        for (int k = 32; k < 64; k++) {
            float v = c[k];
            s1 += v * v;
            g_cb_h[i * CODE_DIM + k] = __float2half(v);
        }
        g_cc[i] = (s0 + s1) + 256.0f;
    }
}

// ---------------- asm helpers ----------------
__device__ __forceinline__ void ldsm4(uint32_t (&r)[4], uint32_t addr) {
    asm volatile("ldmatrix.sync.aligned.m8n8.x4.shared.b16 {%0,%1,%2,%3}, [%4];"
                 : "=r"(r[0]), "=r"(r[1]), "=r"(r[2]), "=r"(r[3]) : "r"(addr));
}
__device__ __forceinline__ void mma16816(float (&d)[4], const uint32_t (&a)[4],
                                         const uint32_t* b) {
    asm volatile("mma.sync.aligned.m16n8k16.row.col.f32.f16.f16.f32 "
                 "{%0,%1,%2,%3}, {%4,%5,%6,%7}, {%8,%9}, {%0,%1,%2,%3};"
                 : "+f"(d[0]), "+f"(d[1]), "+f"(d[2]), "+f"(d[3])
                 : "r"(a[0]), "r"(a[1]), "r"(a[2]), "r"(a[3]),
                   "r"(b[0]), "r"(b[1]));
}
__device__ __forceinline__ void cp_async16(uint32_t dst, const void* src) {
    asm volatile("cp.async.cg.shared.global [%0], [%1], 16;" :: "r"(dst), "l"(src));
}
#define CP_COMMIT() asm volatile("cp.async.commit_group;")
#define CP_WAIT1()  asm volatile("cp.async.wait_group 1;" ::: "memory")
#define CP_WAIT0()  asm volatile("cp.async.wait_group 0;" ::: "memory")

// exact round-2-style d2 (sequential-FMA dot, half-split sumsq, (zz-2a)+cc)
__device__ __forceinline__ float exact_d2_g(const float* __restrict__ zrow,
                                            const float* __restrict__ c, float zz) {
    float a = 0.0f;
    for (int k = 0; k < CODE_DIM; k++) a = fmaf(zrow[k], c[k], a);
    float c0 = 0.0f, c1 = 0.0f;
    for (int k = 0; k < 32; k++)  { float v = c[k]; c0 += v * v; }
    for (int k = 32; k < 64; k++) { float v = c[k]; c1 += v * v; }
    return (zz - 2.0f * a) + (c0 + c1);
}

// merge two sorted triples -> sorted top-3 of the six
__device__ __forceinline__ void merge3(unsigned long long& a1, unsigned long long& a2,
                                       unsigned long long& a3,
                                       unsigned long long b1, unsigned long long b2,
                                       unsigned long long b3) {
    unsigned long long lo1 = min(a1, b1), hi1 = max(a1, b1);
    unsigned long long lo2 = min(a2, b2), hi2 = max(a2, b2);
    a1 = lo1;
    unsigned long long t = min(hi1, lo2), u = max(hi1, lo2);
    a2 = t;
    a3 = min(u, min(hi2, min(a3, b3)));
}

// smem byte offsets
#define OFF_ZH   0               // 128 x 72 fp16 = 18432
#define OFF_CH   18432           // 2 bufs x 18432
#define OFF_CC   55296           // 2 bufs x 512
#define OFF_RED  56320           // 128 x 4 x 32B = 16384
#define OFF_LP   72704           // 32 floats
#define SMEM_TOTAL 72832

// ---------------- main: 1-pass fp16 mma screen + top-3 + exact rescore ----------------
// 256 threads, 8 warps as 2(M) x 4(N); block = 128 tokens x 1024 codes (8 tiles of 128).
__global__ __launch_bounds__(256, 1)
void vq_main(const float* __restrict__ z, const float* __restrict__ codebook,
             float* __restrict__ out_q, float* __restrict__ out_idx)
{
    extern __shared__ char smem_raw[];
    char* sm = smem_raw;
    const uint32_t sbase = (uint32_t)__cvta_generic_to_shared(sm);

    const int tid = threadIdx.x;
    const int token0 = blockIdx.x * 128;
    const int lane = tid & 31, wid = tid >> 5;
    const int wm = wid >> 2, wn = wid & 3;
    const int lrow = lane & 7, lmat = lane >> 3;
    const int g = lane >> 2, q4 = lane & 3;

    // ---- prefetch codebook tile 0 (buf 0) + cc via cp.async ----
    #pragma unroll
    for (int j = 0; j < 4; j++) {
        int c = tid + j * 256;                 // 0..1023 16B chunks
        int r = c >> 3, k16 = c & 7;
        const __half* src = g_cb_h + (size_t)r * 64 + k16 * 8;
        cp_async16(sbase + OFF_CH + r * 144 + k16 * 16, src);
    }
    if (tid < 32) cp_async16(sbase + OFF_CC + tid * 16, g_cc + tid * 4);
    CP_COMMIT();

    // ---- z tile: fp16 into smem (stride 72) ----
    {
        int r = tid >> 1, h = tid & 1;
        const float4* zp = (const float4*)(z + (size_t)(token0 + r) * CODE_DIM) + h * 8;
        __half* zh = (__half*)(sm + OFF_ZH) + r * 72 + h * 32;
        #pragma unroll
        for (int v = 0; v < 8; v++) {
            float4 t4 = zp[v];
            zh[v * 4 + 0] = __float2half(t4.x);
            zh[v * 4 + 1] = __float2half(t4.y);
            zh[v * 4 + 2] = __float2half(t4.z);
            zh[v * 4 + 3] = __float2half(t4.w);
        }
    }

    // ldmatrix addressing (proven R5 mapping)
    const int a_row = wm * 64 + (lmat & 1) * 8 + lrow;
    const int a_kof = (lmat >> 1) * 8;
    const int b_row = wn * 32 + (lmat >> 1) * 8 + lrow;
    const int b_kof = (lmat & 1) * 8;

    // sorted top-3 trackers per (row, c): keys = (bits(s)&~31) | (ct*4+nf)
    int k3[8][2][3];
    #pragma unroll
    for (int r = 0; r < 8; r++)
        #pragma unroll
        for (int c = 0; c < 2; c++) {
            k3[r][c][0] = 0x7FFFFFFF; k3[r][c][1] = 0x7FFFFFFF; k3[r][c][2] = 0x7FFFFFFF;
        }

    for (int ct = 0; ct < 8; ct++) {
        const int b = ct & 1;
        if (ct < 7) {        // prefetch tile ct+1 into buf b^1
            const int nb = b ^ 1;
            #pragma unroll
            for (int j = 0; j < 4; j++) {
                int c = tid + j * 256;
                int r = c >> 3, k16 = c & 7;
                const __half* src = g_cb_h + (size_t)((ct + 1) * 128 + r) * 64 + k16 * 8;
                cp_async16(sbase + OFF_CH + nb * 18432 + r * 144 + k16 * 16, src);
            }
            if (tid < 32) cp_async16(sbase + OFF_CC + nb * 512 + tid * 16,
                                     g_cc + (ct + 1) * 128 + tid * 4);
            CP_COMMIT();
            CP_WAIT1();
        } else {
            CP_WAIT0();
        }
        __syncthreads();

        const float* ccs = (const float*)(sm + OFF_CC + b * 512);
        float ccr[8];
        #pragma unroll
        for (int nf = 0; nf < 4; nf++)
            #pragma unroll
            for (int c = 0; c < 2; c++)
                ccr[nf * 2 + c] = ccs[wn * 32 + nf * 8 + q4 * 2 + c];

        float acc[4][4][4];
        #pragma unroll
        for (int mf = 0; mf < 4; mf++)
            #pragma unroll
            for (int nf = 0; nf < 4; nf++)
                #pragma unroll
                for (int e = 0; e < 4; e++) acc[mf][nf][e] = 0.0f;

        const uint32_t s_ch = sbase + OFF_CH + b * 18432;

        #pragma unroll
        for (int kc = 0; kc < 4; kc++) {
            uint32_t ah[4][4], bh[2][4];
            #pragma unroll
            for (int mf = 0; mf < 4; mf++) {
                uint32_t off = (uint32_t)(((a_row + mf * 16) * 72 + kc * 16 + a_kof) * 2);
                ldsm4(ah[mf], sbase + OFF_ZH + off);
            }
            #pragma unroll
            for (int np = 0; np < 2; np++) {
                uint32_t off = (uint32_t)(((b_row + np * 16) * 72 + kc * 16 + b_kof) * 2);
                ldsm4(bh[np], s_ch + off);
            }
            #pragma unroll
            for (int mf = 0; mf < 4; mf++)
                #pragma unroll
                for (int nf = 0; nf < 4; nf++)
                    mma16816(acc[mf][nf], ah[mf], &bh[nf >> 1][(nf & 1) * 2]);
        }

        // ---- epilogue: s = (cc+256) - 2*dot, sorted top-3 insert (branch-free) ----
        const int idb = ct * 4;
        #pragma unroll
        for (int mf = 0; mf < 4; mf++)
            #pragma unroll
            for (int rr = 0; rr < 2; rr++) {
                const int row = mf * 2 + rr;
                #pragma unroll
                for (int nf = 0; nf < 4; nf++)
                    #pragma unroll
                    for (int c = 0; c < 2; c++) {
                        float s = fmaf(acc[mf][nf][rr * 2 + c], -2.0f, ccr[nf * 2 + c]);
                        int key = (__float_as_int(s) & 0xFFFFFFE0) | (idb + nf);
                        int t1 = max(k3[row][c][0], key);
                        k3[row][c][0] = min(k3[row][c][0], key);
                        int t2 = max(k3[row][c][1], t1);
                        k3[row][c][1] = min(k3[row][c][1], t1);
                        k3[row][c][2] = min(k3[row][c][2], t2);
                    }
            }
        __syncthreads();
    }

    // ---- per-row: 64-bit keys, merge trackers + quad shfl, stash per (token, wn) ----
    ulonglong4* red = (ulonglong4*)(sm + OFF_RED);
    const int base_nc = wn * 32 + q4 * 2;
    #pragma unroll
    for (int row = 0; row < 8; row++) {
        unsigned long long m1, m2, m3;
        {
            unsigned long long kk[2][3];
            #pragma unroll
            for (int c = 0; c < 2; c++)
                #pragma unroll
                for (int j = 0; j < 3; j++) {
                    int k = k3[row][c][j];
                    int id = k & 31;
                    unsigned long long code =
                        (unsigned)((id >> 2) * 128 + (id & 3) * 8 + base_nc + c);
                    kk[c][j] = ((unsigned long long)(unsigned)(k & 0xFFFFFFE0) << 10) | code;
                }
            m1 = kk[0][0]; m2 = kk[0][1]; m3 = kk[0][2];
            merge3(m1, m2, m3, kk[1][0], kk[1][1], kk[1][2]);
        }
        #pragma unroll
        for (int m = 1; m <= 2; m <<= 1) {
            unsigned long long M1 = __shfl_xor_sync(0xffffffffu, m1, m);
            unsigned long long M2 = __shfl_xor_sync(0xffffffffu, m2, m);
            unsigned long long M3 = __shfl_xor_sync(0xffffffffu, m3, m);
            merge3(m1, m2, m3, M1, M2, M3);
        }
        if (q4 == 0) {
            int tok = wm * 64 + (row >> 1) * 16 + (row & 1) * 8 + g;
            red[tok * 4 + wn] = make_ulonglong4(m1, m2, m3, 0ull);
        }
    }
    __syncthreads();

    // ---- writer: final merge, rescore near-ties, outputs + scatter stats ----
    float lsum = 0.0f;
    if (tid < 128) {
        const int t = tid;
        ulonglong4 p = red[t * 4];
        unsigned long long f1 = p.x, f2 = p.y, f3 = p.z;
        #pragma unroll
        for (int w = 1; w < 4; w++) {
            ulonglong4 q = red[t * 4 + w];
            merge3(f1, f2, f3, q.x, q.y, q.z);
        }
        int bi = (int)(f1 & 1023);
        const int token = token0 + t;
        const float* zrow = z + (size_t)token * CODE_DIM;

        float s1 = __int_as_float((int)(f1 >> 10));
        float s2 = __int_as_float((int)(f2 >> 10));
        if (s2 - s1 < 0.1f) {
            // near-tie: exact rescore of the screened top-3 (verified arithmetic)
            int c2 = (int)(f2 & 1023), c3 = (int)(f3 & 1023);
            float a0 = 0.0f, a1 = 0.0f;
            for (int k = 0; k < 32; k++)  { float v = zrow[k]; a0 += v * v; }
            for (int k = 32; k < 64; k++) { float v = zrow[k]; a1 += v * v; }
            float zz = a0 + a1;
            float d1 = exact_d2_g(zrow, codebook + (size_t)bi * CODE_DIM, zz);
            float d2 = exact_d2_g(zrow, codebook + (size_t)c2 * CODE_DIM, zz);
            float d3 = exact_d2_g(zrow, codebook + (size_t)c3 * CODE_DIM, zz);
            float bd = d1;
            if (d2 < bd || (d2 == bd && c2 < bi)) { bd = d2; bi = c2; }
            if (d3 < bd || (d3 == bd && c3 < bi)) { bd = d3; bi = c3; }
        }

        out_idx[token] = (float)bi;
        atomicAdd(&g_counts[bi], 1.0f);

        const float4* cb = (const float4*)(codebook + (size_t)bi * CODE_DIM);
        const float4* zp = (const float4*)zrow;
        float4* qo = (float4*)(out_q + (size_t)token * CODE_DIM);
        #pragma unroll
        for (int v = 0; v < 16; v++) {
            float4 q = cb[v];
            float4 zv = zp[v];
            int k = v * 4;
            float d0 = zv.x - q.x, d1 = zv.y - q.y, d2 = zv.z - q.z, d3 = zv.w - q.w;
            lsum += d0 * d0; lsum += d1 * d1; lsum += d2 * d2; lsum += d3 * d3;
            qo[v] = q;
            atomicAdd(&g_dw[bi * CODE_DIM + k + 0], zv.x);
            atomicAdd(&g_dw[bi * CODE_DIM + k + 1], zv.y);
            atomicAdd(&g_dw[bi * CODE_DIM + k + 2], zv.z);
            atomicAdd(&g_dw[bi * CODE_DIM + k + 3], zv.w);
        }
    }

    // ---- block reduction of commitment-loss partial ----
    #pragma unroll
    for (int o = 16; o > 0; o >>= 1) lsum += __shfl_down_sync(0xffffffffu, lsum, o);
    float* lpart = (float*)(sm + OFF_LP);
    if ((tid & 31) == 0) lpart[tid >> 5] = lsum;
    __syncthreads();
    if (tid == 0) {
        float s = 0.0f;
        #pragma unroll
        for (int w = 0; w < 8; w++) s += lpart[w];
        atomicAdd(&g_loss, s);
    }
}

// ---------------- finalize 1: new_cluster_size + its sum ----------------
__global__ void vq_final_cs(const float* __restrict__ cluster_size,
                            float* __restrict__ out_cs)
{
    int t = threadIdx.x;  // 1024 threads, 1 block
    float ncs = 0.99f * cluster_size[t] + 0.01f * g_counts[t];
    out_cs[t] = ncs;
    g_ncs[t] = ncs;

    float s = ncs;
    #pragma unroll
    for (int o = 16; o > 0; o >>= 1) s += __shfl_down_sync(0xffffffffu, s, o);
    __shared__ float p[32];
    if ((t & 31) == 0) p[t >> 5] = s;
    __syncthreads();
    if (t < 32) {
        float v = p[t];
        #pragma unroll
        for (int o = 16; o > 0; o >>= 1) v += __shfl_down_sync(0xffffffffu, v, o);
        if (t == 0) g_n = v;
    }
}

// ---------------- finalize 2: new_ema_w, new_codebook, loss ----------------
__global__ void vq_final_cb(const float* __restrict__ ema_w,
                            float* __restrict__ out_ew,
                            float* __restrict__ out_cb,
                            float* __restrict__ out_loss)
{
    int i = blockIdx.x * blockDim.x + threadIdx.x;  // 65536
    float e = 0.99f * ema_w[i] + 0.01f * g_dw[i];
    out_ew[i] = e;
    int k = i >> 6;
    float n = g_n;
    float cs = (g_ncs[k] + 1e-5f) / (n + 1024.0f * 1e-5f) * n;
    out_cb[i] = e / cs;
    if (i == 0) out_loss[0] = g_loss * (1.0f / 8388608.0f);  // 2^-23 == 1/(N*D)
}

// ---------------- launch ----------------
extern "C" void kernel_launch(void* const* d_in, const int* in_sizes, int n_in,
                              void* d_out, int out_size)
{
    const float* z            = (const float*)d_in[0];
    const float* codebook     = (const float*)d_in[1];
    const float* cluster_size = (const float*)d_in[2];
    const float* ema_w        = (const float*)d_in[3];
    float* out = (float*)d_out;

    // output packing: quantized_st | indices | loss | new_codebook | new_cluster_size | new_ema_w
    const size_t OFF_Q    = 0;
    const size_t OFF_IDX  = (size_t)N_TOKENS * CODE_DIM;          // 8388608
    const size_t OFF_LOSS = OFF_IDX + N_TOKENS;                   // 8519680
    const size_t OFF_CB   = OFF_LOSS + 1;                         // 8519681
    const size_t OFF_CS   = OFF_CB + NUM_CODES * CODE_DIM;        // 8585217
    const size_t OFF_EW   = OFF_CS + NUM_CODES;                   // 8586241

    cudaFuncSetAttribute(vq_main, cudaFuncAttributeMaxDynamicSharedMemorySize, SMEM_TOTAL);

    vq_prep<<<256, 256>>>(codebook);
    vq_main<<<N_TOKENS / 128, 256, SMEM_TOTAL>>>(z, codebook, out + OFF_Q, out + OFF_IDX);
    vq_final_cs<<<1, NUM_CODES>>>(cluster_size, out + OFF_CS);
    vq_final_cb<<<(NUM_CODES * CODE_DIM) / 256, 256>>>(ema_w, out + OFF_EW,
                                                       out + OFF_CB, out + OFF_LOSS);
}